// round 6
// baseline (speedup 1.0000x reference)
#include <cuda_runtime.h>
#include <cstdint>
#include <cstddef>

// ---------------- problem constants ----------------
#define S2_  32
#define B_   32
#define CI_  64
#define CO_  64
#define L_   256
#define K_   3
#define A_   16
#define H_   128
#define NW_  12288     // CI*CO*K  (flat hyper-weight dim)
#define BL_  8192      // B*L
#define COK_ 192       // CO*K
#define CIK_ 192       // CI*K

// ---------------- device scratch (static, allowed) ----------------
__device__ float g_HH[BL_ * H_];          // 4 MB   relu(LN(z@W1))
__device__ float g_BIAS[BL_ * CO_];       // 2 MB   bias[b,l,o]
__device__ float g_W2p[H_ * NW_];         // 6 MB   W2 permuted to [h][(i*K+k)*CO+o]
__device__ float g_b2p[NW_];              //        b2 permuted likewise
__device__ float g_W[(size_t)BL_ * NW_];  // 403 MB generated conv weights [bl][(i*K+k)*CO+o]

// =================================================================
// Kernel 1: hypernets.  One block per (b,l); 128 threads (= H).
// Computes h = relu(LN(z@W1+b1)) -> g_HH, and hb -> bias -> g_BIAS.
// =================================================================
__global__ void __launch_bounds__(128) hyper_kernel(
    const float* __restrict__ z,
    const float* __restrict__ W1, const float* __restrict__ b1,
    const float* __restrict__ g1, const float* __restrict__ be1,
    const float* __restrict__ Wb1, const float* __restrict__ bb1,
    const float* __restrict__ gb1, const float* __restrict__ beb1,
    const float* __restrict__ Wb2, const float* __restrict__ bb2)
{
    int bl = blockIdx.x;
    int t  = threadIdx.x;

    __shared__ float sz[A_];
    __shared__ float red[16];
    __shared__ float sh2[H_];

    if (t < A_) sz[t] = z[bl * A_ + t];
    __syncthreads();

    float a1 = b1[t], a2 = bb1[t];
#pragma unroll
    for (int a = 0; a < A_; ++a) {
        float zv = sz[a];
        a1 = fmaf(zv, W1[a * H_ + t], a1);
        a2 = fmaf(zv, Wb1[a * H_ + t], a2);
    }

    // block-wide mean/var for both pre-activations
    float s1 = a1, q1 = a1 * a1, s2 = a2, q2 = a2 * a2;
#pragma unroll
    for (int off = 16; off > 0; off >>= 1) {
        s1 += __shfl_xor_sync(0xffffffffu, s1, off);
        q1 += __shfl_xor_sync(0xffffffffu, q1, off);
        s2 += __shfl_xor_sync(0xffffffffu, s2, off);
        q2 += __shfl_xor_sync(0xffffffffu, q2, off);
    }
    int w = t >> 5;
    if ((t & 31) == 0) { red[w] = s1; red[4 + w] = q1; red[8 + w] = s2; red[12 + w] = q2; }
    __syncthreads();

    float S1 = red[0] + red[1] + red[2] + red[3];
    float Q1 = red[4] + red[5] + red[6] + red[7];
    float S2 = red[8] + red[9] + red[10] + red[11];
    float Q2 = red[12] + red[13] + red[14] + red[15];

    const float inv_h = 1.0f / (float)H_;
    float mu1 = S1 * inv_h, mu2 = S2 * inv_h;
    float v1 = Q1 * inv_h - mu1 * mu1;
    float v2 = Q2 * inv_h - mu2 * mu2;
    float i1 = rsqrtf(v1 + 1e-5f);
    float i2 = rsqrtf(v2 + 1e-5f);

    float h1 = fmaxf(fmaf((a1 - mu1) * i1, g1[t], be1[t]), 0.0f);
    float h2 = fmaxf(fmaf((a2 - mu2) * i2, gb1[t], beb1[t]), 0.0f);

    g_HH[bl * H_ + t] = h1;
    sh2[t] = h2;
    __syncthreads();

    if (t < CO_) {
        float acc = bb2[t];
#pragma unroll 8
        for (int h = 0; h < H_; ++h) acc = fmaf(sh2[h], Wb2[h * CO_ + t], acc);
        g_BIAS[bl * CO_ + t] = acc;
    }
}

// =================================================================
// Kernel 2: permute W2 columns  (i*COK + o*K + k) -> ((i*K+k)*CO + o)
// =================================================================
__global__ void permute_kernel(const float* __restrict__ W2, const float* __restrict__ b2)
{
    int idx = blockIdx.x * blockDim.x + threadIdx.x;
    if (idx >= H_ * NW_) return;
    int h = idx / NW_;
    int c = idx - h * NW_;
    int i   = c / COK_;
    int rem = c - i * COK_;
    int o   = rem / K_;
    int k   = rem - o * K_;
    int cp  = (i * K_ + k) * CO_ + o;
    g_W2p[h * NW_ + cp] = W2[idx];
    if (h == 0) g_b2p[cp] = b2[c];
}

// =================================================================
// Kernel 3: W = HH @ W2p + b2p   (M=8192, N=12288, K=128)  TF32 MMA
//   128x128 block tile, full-K in smem (stride 136 -> conflict-free
//   m16n8k8 fragment loads), 8 warps in a 2(M) x 4(N) grid, each
//   warp computes 64x32 via 4x4 mma tiles.
// =================================================================
#define WG_STRIDE 136
#define WG_SMEM_BYTES (2 * 128 * WG_STRIDE * 4)

__device__ __forceinline__ uint32_t f2tf32(float f)
{
    uint32_t r;
    asm("cvt.rna.tf32.f32 %0, %1;" : "=r"(r) : "f"(f));
    return r;
}

__global__ void __launch_bounds__(256) wgen_kernel()
{
    extern __shared__ uint32_t wsm[];
    uint32_t* As = wsm;                      // [128][136] tf32 of HH
    uint32_t* Bs = wsm + 128 * WG_STRIDE;    // [128][136] tf32 of W2p (k-major)

    int m0 = blockIdx.y * 128;
    int n0 = blockIdx.x * 128;
    int tid = threadIdx.x;

    for (int idx = tid; idx < 128 * 32; idx += 256) {
        int r = idx >> 5, c4 = (idx & 31) << 2;
        float4 v = *reinterpret_cast<const float4*>(&g_HH[(size_t)(m0 + r) * H_ + c4]);
        uint32_t* d = &As[r * WG_STRIDE + c4];
        d[0] = f2tf32(v.x); d[1] = f2tf32(v.y); d[2] = f2tf32(v.z); d[3] = f2tf32(v.w);
    }
    for (int idx = tid; idx < 128 * 32; idx += 256) {
        int r = idx >> 5, c4 = (idx & 31) << 2;
        float4 v = *reinterpret_cast<const float4*>(&g_W2p[(size_t)r * NW_ + n0 + c4]);
        uint32_t* d = &Bs[r * WG_STRIDE + c4];
        d[0] = f2tf32(v.x); d[1] = f2tf32(v.y); d[2] = f2tf32(v.z); d[3] = f2tf32(v.w);
    }
    __syncthreads();

    int warp = tid >> 5, lane = tid & 31;
    int wm = (warp >> 2) * 64;   // 2 warps along M
    int wn = (warp & 3) * 32;    // 4 warps along N
    int gr = lane >> 2, tg = lane & 3;

    float acc[4][4][4];
#pragma unroll
    for (int a = 0; a < 4; ++a)
#pragma unroll
        for (int b = 0; b < 4; ++b)
#pragma unroll
            for (int c = 0; c < 4; ++c) acc[a][b][c] = 0.0f;

#pragma unroll 2
    for (int ks = 0; ks < 16; ++ks) {
        int kb = ks * 8;
        uint32_t af[4][4], bf[4][2];
#pragma unroll
        for (int tm = 0; tm < 4; ++tm) {
            int r = wm + tm * 16 + gr;
            af[tm][0] = As[r * WG_STRIDE + kb + tg];
            af[tm][1] = As[(r + 8) * WG_STRIDE + kb + tg];
            af[tm][2] = As[r * WG_STRIDE + kb + tg + 4];
            af[tm][3] = As[(r + 8) * WG_STRIDE + kb + tg + 4];
        }
#pragma unroll
        for (int tn = 0; tn < 4; ++tn) {
            int c = wn + tn * 8 + gr;
            bf[tn][0] = Bs[(kb + tg) * WG_STRIDE + c];
            bf[tn][1] = Bs[(kb + tg + 4) * WG_STRIDE + c];
        }
#pragma unroll
        for (int tm = 0; tm < 4; ++tm)
#pragma unroll
            for (int tn = 0; tn < 4; ++tn)
                asm volatile(
                    "mma.sync.aligned.m16n8k8.row.col.f32.tf32.tf32.f32 "
                    "{%0,%1,%2,%3}, {%4,%5,%6,%7}, {%8,%9}, {%0,%1,%2,%3};"
                    : "+f"(acc[tm][tn][0]), "+f"(acc[tm][tn][1]),
                      "+f"(acc[tm][tn][2]), "+f"(acc[tm][tn][3])
                    : "r"(af[tm][0]), "r"(af[tm][1]), "r"(af[tm][2]), "r"(af[tm][3]),
                      "r"(bf[tn][0]), "r"(bf[tn][1]));
    }

    // epilogue: + b2p, store float2 pairs
#pragma unroll
    for (int tm = 0; tm < 4; ++tm) {
        int r = m0 + wm + tm * 16 + gr;
#pragma unroll
        for (int tn = 0; tn < 4; ++tn) {
            int c = n0 + wn + tn * 8 + tg * 2;
            float2 bia = *reinterpret_cast<const float2*>(&g_b2p[c]);
            float2 v0 = make_float2(acc[tm][tn][0] + bia.x, acc[tm][tn][1] + bia.y);
            float2 v1 = make_float2(acc[tm][tn][2] + bia.x, acc[tm][tn][3] + bia.y);
            *reinterpret_cast<float2*>(&g_W[(size_t)r * NW_ + c]) = v0;
            *reinterpret_cast<float2*>(&g_W[(size_t)(r + 8) * NW_ + c]) = v1;
        }
    }
}

// =================================================================
// Kernel 4: conv.  Block = (b, 2-wide l tile).  256 threads.
//   smem: w tile [2][192][64] (96KB) + x tile [32][64][4] (padded).
//   Thread micro-tile: 4s x 4o for one l.  Output staged to smem,
//   written as float2 (l-pair) rows.
// =================================================================
#define CV_XS_STRIDE 260
#define CV_SMEM_BYTES ((2 * NW_ + S2_ * CV_XS_STRIDE) * 4)

__global__ void __launch_bounds__(256) conv_kernel(
    const float* __restrict__ x, float* __restrict__ out)
{
    extern __shared__ float cs[];
    float* ws = cs;               // [2][12288]
    float* xs = cs + 2 * NW_;     // [32][260]  (i*4 + c, c = col l0-1+c)

    int b  = blockIdx.y;
    int l0 = blockIdx.x * 2;
    int tid = threadIdx.x;

    // load w tile (coalesced float4)
    const float4* Wsrc = reinterpret_cast<const float4*>(g_W + (size_t)(b * L_ + l0) * NW_);
    float4* wd = reinterpret_cast<float4*>(ws);
    for (int idx = tid; idx < 2 * NW_ / 4; idx += 256) wd[idx] = Wsrc[idx];

    // load x tile: cols l0-1 .. l0+2 for every (s,i)
    for (int p = tid; p < S2_ * CI_; p += 256) {
        int s = p >> 6, i = p & 63;
        const float* xr = x + (((size_t)s * B_ + b) * CI_ + i) * L_;
        int gc = l0 - 1;
        float* xd = xs + s * CV_XS_STRIDE + i * 4;
        xd[0] = (gc >= 0) ? xr[gc] : 0.0f;
        xd[1] = xr[gc + 1];
        xd[2] = xr[gc + 2];
        xd[3] = (gc + 3 < L_) ? xr[gc + 3] : 0.0f;
    }
    __syncthreads();

    int dl = tid >> 7;          // which l of the pair
    int r  = tid & 127;
    int s0 = (r >> 4) * 4;
    int o0 = (r & 15) * 4;

    float acc[4][4];
#pragma unroll
    for (int j = 0; j < 4; ++j)
#pragma unroll
        for (int q = 0; q < 4; ++q) acc[j][q] = 0.0f;

    const float* wrow = ws + dl * NW_;
    const float* xrow = xs + s0 * CV_XS_STRIDE + dl;

#pragma unroll 4
    for (int i = 0; i < CI_; ++i) {
        float xa[4][3];
#pragma unroll
        for (int j = 0; j < 4; ++j) {
            const float* xp = xrow + j * CV_XS_STRIDE + i * 4;
            xa[j][0] = xp[0]; xa[j][1] = xp[1]; xa[j][2] = xp[2];
        }
#pragma unroll
        for (int k = 0; k < 3; ++k) {
            float4 wv = *reinterpret_cast<const float4*>(wrow + (i * 3 + k) * CO_ + o0);
#pragma unroll
            for (int j = 0; j < 4; ++j) {
                acc[j][0] = fmaf(xa[j][k], wv.x, acc[j][0]);
                acc[j][1] = fmaf(xa[j][k], wv.y, acc[j][1]);
                acc[j][2] = fmaf(xa[j][k], wv.z, acc[j][2]);
                acc[j][3] = fmaf(xa[j][k], wv.w, acc[j][3]);
            }
        }
    }

    // add bias[b, l0+dl, o]
    int bl = b * L_ + l0 + dl;
    float4 bv = *reinterpret_cast<const float4*>(&g_BIAS[(size_t)bl * CO_ + o0]);
#pragma unroll
    for (int j = 0; j < 4; ++j) {
        acc[j][0] += bv.x; acc[j][1] += bv.y; acc[j][2] += bv.z; acc[j][3] += bv.w;
    }
    __syncthreads();   // everyone done reading ws/xs

    // stage output in smem (reuse ws region): os[s][o][dl]
    float* os = cs;
#pragma unroll
    for (int j = 0; j < 4; ++j)
#pragma unroll
        for (int q = 0; q < 4; ++q)
            os[(s0 + j) * 128 + (o0 + q) * 2 + dl] = acc[j][q];
    __syncthreads();

    // coalesced-ish float2 writes: one l-pair per (s,o) row
    for (int p = tid; p < S2_ * CO_; p += 256) {
        int s = p >> 6, o = p & 63;
        float2 v = *reinterpret_cast<float2*>(&os[s * 128 + o * 2]);
        *reinterpret_cast<float2*>(&out[(((size_t)s * B_ + b) * CO_ + o) * L_ + l0]) = v;
    }
}

// =================================================================
// launch
// =================================================================
extern "C" void kernel_launch(void* const* d_in, const int* in_sizes, int n_in,
                              void* d_out, int out_size)
{
    const float* x   = (const float*)d_in[0];
    const float* z   = (const float*)d_in[1];
    const float* W1  = (const float*)d_in[2];
    const float* b1  = (const float*)d_in[3];
    const float* g1  = (const float*)d_in[4];
    const float* be1 = (const float*)d_in[5];
    const float* W2  = (const float*)d_in[6];
    const float* b2  = (const float*)d_in[7];
    const float* Wb1 = (const float*)d_in[8];
    const float* bb1 = (const float*)d_in[9];
    const float* gb1 = (const float*)d_in[10];
    const float* beb1= (const float*)d_in[11];
    const float* Wb2 = (const float*)d_in[12];
    const float* bb2 = (const float*)d_in[13];
    float* out = (float*)d_out;

    cudaFuncSetAttribute(wgen_kernel, cudaFuncAttributeMaxDynamicSharedMemorySize, WG_SMEM_BYTES);
    cudaFuncSetAttribute(conv_kernel, cudaFuncAttributeMaxDynamicSharedMemorySize, CV_SMEM_BYTES);

    hyper_kernel<<<BL_, 128>>>(z, W1, b1, g1, be1, Wb1, bb1, gb1, beb1, Wb2, bb2);
    permute_kernel<<<(H_ * NW_ + 255) / 256, 256>>>(W2, b2);
    wgen_kernel<<<dim3(NW_ / 128, BL_ / 128), 256, WG_SMEM_BYTES>>>();
    conv_kernel<<<dim3(L_ / 2, B_), 256, CV_SMEM_BYTES>>>(x, out);
}

// round 8
// speedup vs baseline: 1.6701x; 1.6701x over previous
#include <cuda_runtime.h>
#include <cstdint>
#include <cstddef>

// ---------------- problem constants ----------------
#define S2_  32
#define B_   32
#define CI_  64
#define CO_  64
#define L_   256
#define K_   3
#define A_   16
#define H_   128
#define NW_  12288     // CI*CO*K  (flat hyper-weight dim)
#define BL_  8192      // B*L
#define COK_ 192       // CO*K

// ---------------- device scratch (static, allowed) ----------------
__device__ float g_HH[BL_ * H_];          // 4 MB   relu(LN(z@W1))
__device__ float g_BIAS[BL_ * CO_];       // 2 MB   bias[b,l,o]
__device__ float g_W2p[H_ * NW_];         // 6 MB   W2 permuted to B-fragment order
__device__ float g_b2p[NW_];              //        b2 permuted likewise
__device__ float g_W[(size_t)BL_ * NW_];  // 403 MB generated conv weights (fragment order, tf32-rounded)

__device__ __forceinline__ uint32_t f2tf32(float f)
{
    uint32_t r;
    asm("cvt.rna.tf32.f32 %0, %1;" : "=r"(r) : "f"(f));
    return r;
}

// =================================================================
// Kernel 1: hypernets.  One block per (b,l); 128 threads (= H).
// =================================================================
__global__ void __launch_bounds__(128) hyper_kernel(
    const float* __restrict__ z,
    const float* __restrict__ W1, const float* __restrict__ b1,
    const float* __restrict__ g1, const float* __restrict__ be1,
    const float* __restrict__ Wb1, const float* __restrict__ bb1,
    const float* __restrict__ gb1, const float* __restrict__ beb1,
    const float* __restrict__ Wb2, const float* __restrict__ bb2)
{
    int bl = blockIdx.x;
    int t  = threadIdx.x;

    __shared__ float sz[A_];
    __shared__ float red[16];
    __shared__ float sh2[H_];

    if (t < A_) sz[t] = z[bl * A_ + t];
    __syncthreads();

    float a1 = b1[t], a2 = bb1[t];
#pragma unroll
    for (int a = 0; a < A_; ++a) {
        float zv = sz[a];
        a1 = fmaf(zv, W1[a * H_ + t], a1);
        a2 = fmaf(zv, Wb1[a * H_ + t], a2);
    }

    float s1 = a1, q1 = a1 * a1, s2 = a2, q2 = a2 * a2;
#pragma unroll
    for (int off = 16; off > 0; off >>= 1) {
        s1 += __shfl_xor_sync(0xffffffffu, s1, off);
        q1 += __shfl_xor_sync(0xffffffffu, q1, off);
        s2 += __shfl_xor_sync(0xffffffffu, s2, off);
        q2 += __shfl_xor_sync(0xffffffffu, q2, off);
    }
    int w = t >> 5;
    if ((t & 31) == 0) { red[w] = s1; red[4 + w] = q1; red[8 + w] = s2; red[12 + w] = q2; }
    __syncthreads();

    float S1 = red[0] + red[1] + red[2] + red[3];
    float Q1 = red[4] + red[5] + red[6] + red[7];
    float S2 = red[8] + red[9] + red[10] + red[11];
    float Q2 = red[12] + red[13] + red[14] + red[15];

    const float inv_h = 1.0f / (float)H_;
    float mu1 = S1 * inv_h, mu2 = S2 * inv_h;
    float v1 = Q1 * inv_h - mu1 * mu1;
    float v2 = Q2 * inv_h - mu2 * mu2;
    float i1 = rsqrtf(v1 + 1e-5f);
    float i2 = rsqrtf(v2 + 1e-5f);

    float h1 = fmaxf(fmaf((a1 - mu1) * i1, g1[t], be1[t]), 0.0f);
    float h2 = fmaxf(fmaf((a2 - mu2) * i2, gb1[t], beb1[t]), 0.0f);

    g_HH[bl * H_ + t] = h1;
    sh2[t] = h2;
    __syncthreads();

    if (t < CO_) {
        float acc = bb2[t];
#pragma unroll 8
        for (int h = 0; h < H_; ++h) acc = fmaf(sh2[h], Wb2[h * CO_ + t], acc);
        g_BIAS[bl * CO_ + t] = acc;
    }
}

// =================================================================
// Kernel 2: permute W2 columns into TF32 m16n8k8 B-fragment order.
//   logical (ik = i*K+k, o)  ->  physical f:
//     ks = ik>>3, t8 = ik&7, r = (t8>=4), tg = t8&3
//     nt = o>>3,  gr = o&7,  lane = gr*4+tg
//     f  = ks*512 + nt*64 + lane*2 + r
// =================================================================
__global__ void permute_kernel(const float* __restrict__ W2, const float* __restrict__ b2)
{
    int idx = blockIdx.x * blockDim.x + threadIdx.x;
    if (idx >= H_ * NW_) return;
    int h = idx / NW_;
    int c = idx - h * NW_;
    int i   = c / COK_;
    int rem = c - i * COK_;
    int o   = rem / K_;
    int k   = rem - o * K_;
    int ik  = i * K_ + k;

    int ks = ik >> 3;
    int t8 = ik & 7;
    int r  = (t8 >= 4) ? 1 : 0;
    int tg = t8 & 3;
    int nt = o >> 3;
    int gr = o & 7;
    int lane = gr * 4 + tg;
    int f = ks * 512 + nt * 64 + lane * 2 + r;

    g_W2p[h * NW_ + f] = W2[idx];
    if (h == 0) g_b2p[f] = b2[c];
}

// =================================================================
// Kernel 3: W = HH @ W2p + b2p   (M=8192, N=12288, K=128)  TF32 MMA
//   As stride 132 (A-frag conflict-free), Bs stride 136 (B-frag
//   conflict-free).  Epilogue stores tf32-rounded values.
// =================================================================
#define WG_AS 132
#define WG_BS 136
#define WG_SMEM_BYTES ((128 * WG_AS + 128 * WG_BS) * 4)

__global__ void __launch_bounds__(256) wgen_kernel()
{
    extern __shared__ uint32_t wsm[];
    uint32_t* As = wsm;                   // [128][132] tf32 of HH
    uint32_t* Bs = wsm + 128 * WG_AS;     // [128][136] tf32 of W2p (k-major)

    int m0 = blockIdx.y * 128;
    int n0 = blockIdx.x * 128;
    int tid = threadIdx.x;

    for (int idx = tid; idx < 128 * 32; idx += 256) {
        int r = idx >> 5, c4 = (idx & 31) << 2;
        float4 v = *reinterpret_cast<const float4*>(&g_HH[(size_t)(m0 + r) * H_ + c4]);
        uint32_t* d = &As[r * WG_AS + c4];
        d[0] = f2tf32(v.x); d[1] = f2tf32(v.y); d[2] = f2tf32(v.z); d[3] = f2tf32(v.w);
    }
    for (int idx = tid; idx < 128 * 32; idx += 256) {
        int r = idx >> 5, c4 = (idx & 31) << 2;
        float4 v = *reinterpret_cast<const float4*>(&g_W2p[(size_t)r * NW_ + n0 + c4]);
        uint32_t* d = &Bs[r * WG_BS + c4];
        d[0] = f2tf32(v.x); d[1] = f2tf32(v.y); d[2] = f2tf32(v.z); d[3] = f2tf32(v.w);
    }
    __syncthreads();

    int warp = tid >> 5, lane = tid & 31;
    int wm = (warp >> 2) * 64;
    int wn = (warp & 3) * 32;
    int gr = lane >> 2, tg = lane & 3;

    float acc[4][4][4];
#pragma unroll
    for (int a = 0; a < 4; ++a)
#pragma unroll
        for (int b = 0; b < 4; ++b)
#pragma unroll
            for (int c = 0; c < 4; ++c) acc[a][b][c] = 0.0f;

#pragma unroll 2
    for (int ks = 0; ks < 16; ++ks) {
        int kb = ks * 8;
        uint32_t af[4][4], bf[4][2];
#pragma unroll
        for (int tm = 0; tm < 4; ++tm) {
            int r = wm + tm * 16 + gr;
            af[tm][0] = As[r * WG_AS + kb + tg];
            af[tm][1] = As[(r + 8) * WG_AS + kb + tg];
            af[tm][2] = As[r * WG_AS + kb + tg + 4];
            af[tm][3] = As[(r + 8) * WG_AS + kb + tg + 4];
        }
#pragma unroll
        for (int tn = 0; tn < 4; ++tn) {
            int c = wn + tn * 8 + gr;
            bf[tn][0] = Bs[(kb + tg) * WG_BS + c];
            bf[tn][1] = Bs[(kb + tg + 4) * WG_BS + c];
        }
#pragma unroll
        for (int tm = 0; tm < 4; ++tm)
#pragma unroll
            for (int tn = 0; tn < 4; ++tn)
                asm volatile(
                    "mma.sync.aligned.m16n8k8.row.col.f32.tf32.tf32.f32 "
                    "{%0,%1,%2,%3}, {%4,%5,%6,%7}, {%8,%9}, {%0,%1,%2,%3};"
                    : "+f"(acc[tm][tn][0]), "+f"(acc[tm][tn][1]),
                      "+f"(acc[tm][tn][2]), "+f"(acc[tm][tn][3])
                    : "r"(af[tm][0]), "r"(af[tm][1]), "r"(af[tm][2]), "r"(af[tm][3]),
                      "r"(bf[tn][0]), "r"(bf[tn][1]));
    }

    // epilogue: + b2p, round to tf32 (conv's mma reads these bits), store float2
#pragma unroll
    for (int tm = 0; tm < 4; ++tm) {
        int r = m0 + wm + tm * 16 + gr;
#pragma unroll
        for (int tn = 0; tn < 4; ++tn) {
            int c = n0 + wn + tn * 8 + tg * 2;
            float2 bia = *reinterpret_cast<const float2*>(&g_b2p[c]);
            float2 v0, v1;
            v0.x = __uint_as_float(f2tf32(acc[tm][tn][0] + bia.x));
            v0.y = __uint_as_float(f2tf32(acc[tm][tn][1] + bia.y));
            v1.x = __uint_as_float(f2tf32(acc[tm][tn][2] + bia.x));
            v1.y = __uint_as_float(f2tf32(acc[tm][tn][3] + bia.y));
            *reinterpret_cast<float2*>(&g_W[(size_t)r * NW_ + c]) = v0;
            *reinterpret_cast<float2*>(&g_W[(size_t)(r + 8) * NW_ + c]) = v1;
        }
    }
}

// =================================================================
// Kernel 4: conv via TF32 tensor cores, W streamed straight from
//   global memory in fragment order (no W smem tile at all).
//   Block = (b, 8 l's), 8 warps, warp = one l:
//     OUT[s=32, o=64] = XU[s=32, ik=192] @ W_l[ik=192, o=64]
// =================================================================
#define CV_SS 649                         // xs row stride
#define CV_OSS 520                        // out-stage stride per s
#define CV_SMEM_BYTES ((32 * CV_SS + 512) * 4)

__global__ void __launch_bounds__(256) conv_kernel(
    const float* __restrict__ x, float* __restrict__ out)
{
    extern __shared__ float cs[];
    float* xs = cs;                 // [32 s][64 i][10 c] tf32 bits, stride CV_SS per s
    float* sb = cs + 32 * CV_SS;    // [8 l][64 o] bias

    int b  = blockIdx.y;
    int l0 = blockIdx.x * 8;
    int tid = threadIdx.x;

    // x window: cols l0-1 .. l0+8, tf32-rounded
    for (int p = tid; p < S2_ * CI_; p += 256) {
        int s = p >> 6, i = p & 63;
        const float* xr = x + (((size_t)s * B_ + b) * CI_ + i) * L_;
        float* xd = xs + s * CV_SS + i * 10;
#pragma unroll
        for (int c = 0; c < 10; ++c) {
            int gc = l0 - 1 + c;
            float v = (gc >= 0 && gc < L_) ? xr[gc] : 0.0f;
            xd[c] = __uint_as_float(f2tf32(v));
        }
    }
    for (int p = tid; p < 8 * CO_; p += 256)
        sb[p] = g_BIAS[((size_t)b * L_ + l0 + (p >> 6)) * CO_ + (p & 63)];
    __syncthreads();

    int wl = tid >> 5, lane = tid & 31;
    int gr = lane >> 2, tg = lane & 3;

    const float2* wp = reinterpret_cast<const float2*>(g_W + (size_t)(b * L_ + l0 + wl) * NW_);

    float acc[2][8][4];
#pragma unroll
    for (int mt = 0; mt < 2; ++mt)
#pragma unroll
        for (int nt = 0; nt < 8; ++nt)
#pragma unroll
            for (int q = 0; q < 4; ++q) acc[mt][nt][q] = 0.0f;

    float2 bb[3][8];
#pragma unroll
    for (int nt = 0; nt < 8; ++nt) bb[0][nt] = wp[nt * 32 + lane];
#pragma unroll
    for (int nt = 0; nt < 8; ++nt) bb[1][nt] = wp[256 + nt * 32 + lane];

    const uint32_t* xu = reinterpret_cast<const uint32_t*>(xs);
    int r0 = gr * CV_SS, r1 = (gr + 8) * CV_SS;
    int r2 = (gr + 16) * CV_SS, r3 = (gr + 24) * CV_SS;

#pragma unroll
    for (int ks = 0; ks < 24; ++ks) {
        if (ks < 22) {
#pragma unroll
            for (int nt = 0; nt < 8; ++nt)
                bb[(ks + 2) % 3][nt] = wp[(ks + 2) * 256 + nt * 32 + lane];
        }
        int e0 = ks * 8 + tg, e1 = e0 + 4;
        int i0 = (e0 * 2731) >> 13, k0 = e0 - i0 * 3;
        int i1 = (e1 * 2731) >> 13, k1 = e1 - i1 * 3;
        int off0 = i0 * 10 + k0 + wl;
        int off1 = i1 * 10 + k1 + wl;
        uint32_t a0 = xu[r0 + off0], a1 = xu[r1 + off0];
        uint32_t a2 = xu[r0 + off1], a3 = xu[r1 + off1];
        uint32_t a4 = xu[r2 + off0], a5 = xu[r3 + off0];
        uint32_t a6 = xu[r2 + off1], a7 = xu[r3 + off1];
        float2* cur = bb[ks % 3];
#pragma unroll
        for (int nt = 0; nt < 8; ++nt) {
            uint32_t w0 = __float_as_uint(cur[nt].x);
            uint32_t w1 = __float_as_uint(cur[nt].y);
            asm volatile(
                "mma.sync.aligned.m16n8k8.row.col.f32.tf32.tf32.f32 "
                "{%0,%1,%2,%3}, {%4,%5,%6,%7}, {%8,%9}, {%0,%1,%2,%3};"
                : "+f"(acc[0][nt][0]), "+f"(acc[0][nt][1]),
                  "+f"(acc[0][nt][2]), "+f"(acc[0][nt][3])
                : "r"(a0), "r"(a1), "r"(a2), "r"(a3), "r"(w0), "r"(w1));
            asm volatile(
                "mma.sync.aligned.m16n8k8.row.col.f32.tf32.tf32.f32 "
                "{%0,%1,%2,%3}, {%4,%5,%6,%7}, {%8,%9}, {%0,%1,%2,%3};"
                : "+f"(acc[1][nt][0]), "+f"(acc[1][nt][1]),
                  "+f"(acc[1][nt][2]), "+f"(acc[1][nt][3])
                : "r"(a4), "r"(a5), "r"(a6), "r"(a7), "r"(w0), "r"(w1));
        }
    }
    __syncthreads();   // all warps done with xs — safe to overwrite with out-stage

    // stage: os[s][wl][o], stride CV_OSS per s (reuses xs region; sb is beyond it)
    float* os = cs;
#pragma unroll
    for (int mt = 0; mt < 2; ++mt) {
        int sA = gr + mt * 16;
#pragma unroll
        for (int nt = 0; nt < 8; ++nt) {
            int o = nt * 8 + tg * 2;
            float2 bv = *reinterpret_cast<const float2*>(&sb[wl * 64 + o]);
            float2 v0, v1;
            v0.x = acc[mt][nt][0] + bv.x; v0.y = acc[mt][nt][1] + bv.y;
            v1.x = acc[mt][nt][2] + bv.x; v1.y = acc[mt][nt][3] + bv.y;
            *reinterpret_cast<float2*>(&os[sA * CV_OSS + wl * 64 + o]) = v0;
            *reinterpret_cast<float2*>(&os[(sA + 8) * CV_OSS + wl * 64 + o]) = v1;
        }
    }
    __syncthreads();

    // coalesced global writes: per (s,o) one row of 8 consecutive l's
    for (int p = tid; p < S2_ * CO_; p += 256) {
        int s = p >> 6, o = p & 63;
        const float* orow = os + s * CV_OSS + o;
        float4 v0, v1;
        v0.x = orow[0];   v0.y = orow[64];  v0.z = orow[128]; v0.w = orow[192];
        v1.x = orow[256]; v1.y = orow[320]; v1.z = orow[384]; v1.w = orow[448];
        float* dst = out + (((size_t)s * B_ + b) * CO_ + o) * L_ + l0;
        *reinterpret_cast<float4*>(dst) = v0;
        *reinterpret_cast<float4*>(dst + 4) = v1;
    }
}

// =================================================================
// launch
// =================================================================
extern "C" void kernel_launch(void* const* d_in, const int* in_sizes, int n_in,
                              void* d_out, int out_size)
{
    const float* x   = (const float*)d_in[0];
    const float* z   = (const float*)d_in[1];
    const float* W1  = (const float*)d_in[2];
    const float* b1  = (const float*)d_in[3];
    const float* g1  = (const float*)d_in[4];
    const float* be1 = (const float*)d_in[5];
    const float* W2  = (const float*)d_in[6];
    const float* b2  = (const float*)d_in[7];
    const float* Wb1 = (const float*)d_in[8];
    const float* bb1 = (const float*)d_in[9];
    const float* gb1 = (const float*)d_in[10];
    const float* beb1= (const float*)d_in[11];
    const float* Wb2 = (const float*)d_in[12];
    const float* bb2 = (const float*)d_in[13];
    float* out = (float*)d_out;

    cudaFuncSetAttribute(wgen_kernel, cudaFuncAttributeMaxDynamicSharedMemorySize, WG_SMEM_BYTES);
    cudaFuncSetAttribute(conv_kernel, cudaFuncAttributeMaxDynamicSharedMemorySize, CV_SMEM_BYTES);

    hyper_kernel<<<BL_, 128>>>(z, W1, b1, g1, be1, Wb1, bb1, gb1, beb1, Wb2, bb2);
    permute_kernel<<<(H_ * NW_ + 255) / 256, 256>>>(W2, b2);
    wgen_kernel<<<dim3(NW_ / 128, BL_ / 128), 256, WG_SMEM_BYTES>>>();
    conv_kernel<<<dim3(L_ / 8, B_), 256, CV_SMEM_BYTES>>>(x, out);
}

// round 12
// speedup vs baseline: 3.7151x; 2.2245x over previous
#include <cuda_runtime.h>
#include <cuda_fp16.h>
#include <cstdint>
#include <cstddef>

// ---------------- problem constants ----------------
#define S2_  32
#define B_   32
#define CI_  64
#define CO_  64
#define L_   256
#define K_   3
#define A_   16
#define H_   128
#define NW_  12288     // CI*CO*K  (flat hyper-weight dim)
#define BL_  8192      // B*L
#define COK_ 192       // CO*K

// ---------------- device scratch (static, allowed) ----------------
__device__ __align__(16) __half g_HH[BL_ * H_];           // 2 MB   relu(LN(z@W1)) in fp16
__device__ float  g_BIAS[BL_ * CO_];                      // 2 MB   bias[b,l,o]
__device__ __align__(16) __half g_W2pT[NW_ * H_];         // 3 MB   W2^T in conv-B-fragment row order: [f][h]
__device__ float  g_b2p[NW_];                             //        b2 permuted to f-space
__device__ __align__(16) __half g_W[(size_t)BL_ * NW_];   // 201 MB generated conv weights, fp16, f-space

__device__ __forceinline__ uint32_t pack_h2(float lo, float hi)
{
    __half2 h = __floats2half2_rn(lo, hi);   // .x = lo (low 16 bits), .y = hi
    return *reinterpret_cast<uint32_t*>(&h);
}

// =================================================================
// Kernel 1: hypernets.  One block per (b,l); 128 threads (= H).
// =================================================================
__global__ void __launch_bounds__(128) hyper_kernel(
    const float* __restrict__ z,
    const float* __restrict__ W1, const float* __restrict__ b1,
    const float* __restrict__ g1, const float* __restrict__ be1,
    const float* __restrict__ Wb1, const float* __restrict__ bb1,
    const float* __restrict__ gb1, const float* __restrict__ beb1,
    const float* __restrict__ Wb2, const float* __restrict__ bb2)
{
    int bl = blockIdx.x;
    int t  = threadIdx.x;

    __shared__ float sz[A_];
    __shared__ float red[16];
    __shared__ float sh2[H_];

    if (t < A_) sz[t] = z[bl * A_ + t];
    __syncthreads();

    float a1 = b1[t], a2 = bb1[t];
#pragma unroll
    for (int a = 0; a < A_; ++a) {
        float zv = sz[a];
        a1 = fmaf(zv, W1[a * H_ + t], a1);
        a2 = fmaf(zv, Wb1[a * H_ + t], a2);
    }

    float s1 = a1, q1 = a1 * a1, s2 = a2, q2 = a2 * a2;
#pragma unroll
    for (int off = 16; off > 0; off >>= 1) {
        s1 += __shfl_xor_sync(0xffffffffu, s1, off);
        q1 += __shfl_xor_sync(0xffffffffu, q1, off);
        s2 += __shfl_xor_sync(0xffffffffu, s2, off);
        q2 += __shfl_xor_sync(0xffffffffu, q2, off);
    }
    int w = t >> 5;
    if ((t & 31) == 0) { red[w] = s1; red[4 + w] = q1; red[8 + w] = s2; red[12 + w] = q2; }
    __syncthreads();

    float S1 = red[0] + red[1] + red[2] + red[3];
    float Q1 = red[4] + red[5] + red[6] + red[7];
    float S2 = red[8] + red[9] + red[10] + red[11];
    float Q2 = red[12] + red[13] + red[14] + red[15];

    const float inv_h = 1.0f / (float)H_;
    float mu1 = S1 * inv_h, mu2 = S2 * inv_h;
    float v1 = Q1 * inv_h - mu1 * mu1;
    float v2 = Q2 * inv_h - mu2 * mu2;
    float i1 = rsqrtf(v1 + 1e-5f);
    float i2 = rsqrtf(v2 + 1e-5f);

    float h1 = fmaxf(fmaf((a1 - mu1) * i1, g1[t], be1[t]), 0.0f);
    float h2 = fmaxf(fmaf((a2 - mu2) * i2, gb1[t], beb1[t]), 0.0f);

    g_HH[bl * H_ + t] = __float2half_rn(h1);
    sh2[t] = h2;
    __syncthreads();

    if (t < CO_) {
        float acc = bb2[t];
#pragma unroll 8
        for (int h = 0; h < H_; ++h) acc = fmaf(sh2[h], Wb2[h * CO_ + t], acc);
        g_BIAS[bl * CO_ + t] = acc;
    }
}

// =================================================================
// Kernel 2: build g_W2pT[f][h] = fp16 of W2[h][c(f)]  (transposed,
//   columns permuted into the m16n8k16 fp16 B-fragment order).
//   f-space: hi = f&1; w = f>>1; r = w&1; lam = (w>>1)&31;
//            nt = (w>>6)&7; ks = w>>9; tg = lam&3; gr = lam>>2;
//            o = nt*8+gr; t16 = r*8 + tg*2 + hi; ik = ks*16 + t16;
//            i = ik/3; k = ik%3; c = i*COK + o*K + k.
//   Thread per (f, h) with h fastest -> coalesced writes.
// =================================================================
__global__ void permute_kernel(const float* __restrict__ W2, const float* __restrict__ b2)
{
    int idx = blockIdx.x * blockDim.x + threadIdx.x;
    if (idx >= NW_ * H_) return;
    int f = idx >> 7;
    int h = idx & 127;

    int hi = f & 1;
    int w  = f >> 1;
    int r  = w & 1;
    int lam = (w >> 1) & 31;
    int nt  = (w >> 6) & 7;
    int ks  = w >> 9;
    int tg = lam & 3, gr = lam >> 2;
    int o  = nt * 8 + gr;
    int t16 = r * 8 + tg * 2 + hi;
    int ik  = ks * 16 + t16;
    int i = (ik * 2731) >> 13;       // exact /3 for ik < 8192
    int k = ik - i * 3;
    int c = i * COK_ + o * K_ + k;

    g_W2pT[(size_t)f * H_ + h] = __float2half_rn(W2[(size_t)h * NW_ + c]);
    if (h == 0) g_b2p[f] = b2[c];
}

// =================================================================
// Kernel 3: W = HH @ W2pT^T + b2p   (M=8192, N=12288, K=128)
//   fp16 m16n8k16 mma, fp32 accum.  Tiles 128x128, K fully resident.
//   As [m][k] halves stride 136, Bs [n][k] halves stride 136 ->
//   all fragment loads are conflict-free 32-bit LDS.
//   smem 68 KB -> 2 CTAs/SM.  Epilogue: +bias, half2 store to g_W.
// =================================================================
#define WG_ST 136                                   // halves per row
#define WG_STW 68                                   // 32-bit words per row
#define WG_SMEM_BYTES (2 * 128 * WG_ST * 2)         // 69632 B

__global__ void __launch_bounds__(256, 2) wgen_kernel()
{
    extern __shared__ __half wsm[];
    __half* As = wsm;                    // [128][136]
    __half* Bs = wsm + 128 * WG_ST;      // [128][136]

    int m0 = blockIdx.y * 128;
    int n0 = blockIdx.x * 128;
    int tid = threadIdx.x;

    // fills: straight uint4 copies (fp16 sources, no conversion)
    {
        const uint4* Asrc = reinterpret_cast<const uint4*>(g_HH);
        uint4* Adst = reinterpret_cast<uint4*>(As);
        const uint4* Bsrc = reinterpret_cast<const uint4*>(g_W2pT);
        uint4* Bdst = reinterpret_cast<uint4*>(Bs);
        for (int idx = tid; idx < 2048; idx += 256) {
            int r = idx >> 4, c = idx & 15;
            Adst[r * 17 + c] = Asrc[(size_t)(m0 + r) * 16 + c];
        }
        for (int idx = tid; idx < 2048; idx += 256) {
            int r = idx >> 4, c = idx & 15;
            Bdst[r * 17 + c] = Bsrc[(size_t)(n0 + r) * 16 + c];
        }
    }
    __syncthreads();

    int warp = tid >> 5, lane = tid & 31;
    int wm = (warp >> 2) * 64;
    int wn = (warp & 3) * 32;
    int gr = lane >> 2, tg = lane & 3;

    float acc[4][4][4];
#pragma unroll
    for (int a = 0; a < 4; ++a)
#pragma unroll
        for (int b = 0; b < 4; ++b)
#pragma unroll
            for (int c = 0; c < 4; ++c) acc[a][b][c] = 0.0f;

    const uint32_t* As32 = reinterpret_cast<const uint32_t*>(As);
    const uint32_t* Bs32 = reinterpret_cast<const uint32_t*>(Bs);

#pragma unroll
    for (int ks = 0; ks < 8; ++ks) {
        int kw = ks * 8 + tg;            // word col of halves (ks*16 + 2tg)
        uint32_t af[4][4], bf[4][2];
#pragma unroll
        for (int tm = 0; tm < 4; ++tm) {
            int row = wm + tm * 16 + gr;
            af[tm][0] = As32[row * WG_STW + kw];
            af[tm][1] = As32[(row + 8) * WG_STW + kw];
            af[tm][2] = As32[row * WG_STW + kw + 4];
            af[tm][3] = As32[(row + 8) * WG_STW + kw + 4];
        }
#pragma unroll
        for (int tn = 0; tn < 4; ++tn) {
            int n = wn + tn * 8 + gr;
            bf[tn][0] = Bs32[n * WG_STW + kw];
            bf[tn][1] = Bs32[n * WG_STW + kw + 4];
        }
#pragma unroll
        for (int tm = 0; tm < 4; ++tm)
#pragma unroll
            for (int tn = 0; tn < 4; ++tn)
                asm volatile(
                    "mma.sync.aligned.m16n8k16.row.col.f32.f16.f16.f32 "
                    "{%0,%1,%2,%3}, {%4,%5,%6,%7}, {%8,%9}, {%0,%1,%2,%3};"
                    : "+f"(acc[tm][tn][0]), "+f"(acc[tm][tn][1]),
                      "+f"(acc[tm][tn][2]), "+f"(acc[tm][tn][3])
                    : "r"(af[tm][0]), "r"(af[tm][1]), "r"(af[tm][2]), "r"(af[tm][3]),
                      "r"(bf[tn][0]), "r"(bf[tn][1]));
    }

    // epilogue: + b2p (fp32), round to fp16, half2 stores
#pragma unroll
    for (int tm = 0; tm < 4; ++tm) {
        int r = m0 + wm + tm * 16 + gr;
#pragma unroll
        for (int tn = 0; tn < 4; ++tn) {
            int f = n0 + wn + tn * 8 + tg * 2;
            float2 bia = *reinterpret_cast<const float2*>(&g_b2p[f]);
            __half2 h0 = __floats2half2_rn(acc[tm][tn][0] + bia.x, acc[tm][tn][1] + bia.y);
            __half2 h1 = __floats2half2_rn(acc[tm][tn][2] + bia.x, acc[tm][tn][3] + bia.y);
            *reinterpret_cast<__half2*>(&g_W[(size_t)r * NW_ + f]) = h0;
            *reinterpret_cast<__half2*>(&g_W[(size_t)(r + 8) * NW_ + f]) = h1;
        }
    }
}

// =================================================================
// Kernel 4: conv via fp16 tensor cores; W streamed from global in
//   fragment order (uint2 per lane, 256B coalesced per (ks,nt)).
//   Block = (b, 8 l's), warp = one l:
//     OUT[s=32, o=64] = X[32 x 192] @ W_l[192 x 64]
//   A packed on the fly from fp32 smem x-window via half2 cvt.
// =================================================================
#define CV_SS 649                         // xs row stride (floats)
#define CV_OSS 520                        // out-stage stride per s
#define CV_SMEM_BYTES ((32 * CV_SS + 512) * 4)

__global__ void __launch_bounds__(256, 2) conv_kernel(
    const float* __restrict__ x, float* __restrict__ out)
{
    extern __shared__ float cs[];
    float* xs = cs;                 // [32 s][64 i][10 c] fp32
    float* sb = cs + 32 * CV_SS;    // [8 l][64 o] bias

    int b  = blockIdx.y;
    int l0 = blockIdx.x * 8;
    int tid = threadIdx.x;

    // x window fill, c-fastest for coalescing: idx -> (s,i,c)
    for (int idx = tid; idx < S2_ * CI_ * 10; idx += 256) {
        int p = idx / 10;
        int c = idx - p * 10;
        int s = p >> 6, i = p & 63;
        int gc = l0 - 1 + c;
        float v = (gc >= 0 && gc < L_) ? x[(((size_t)s * B_ + b) * CI_ + i) * L_ + gc] : 0.0f;
        xs[s * CV_SS + i * 10 + c] = v;
    }
    for (int p = tid; p < 8 * CO_; p += 256)
        sb[p] = g_BIAS[((size_t)b * L_ + l0 + (p >> 6)) * CO_ + (p & 63)];
    __syncthreads();

    int wl = tid >> 5, lane = tid & 31;
    int gr = lane >> 2, tg = lane & 3;

    const uint2* wp = reinterpret_cast<const uint2*>(g_W + (size_t)(b * L_ + l0 + wl) * NW_);

    float acc[2][8][4];
#pragma unroll
    for (int mt = 0; mt < 2; ++mt)
#pragma unroll
        for (int nt = 0; nt < 8; ++nt)
#pragma unroll
            for (int q = 0; q < 4; ++q) acc[mt][nt][q] = 0.0f;

    uint2 bb[2][8];
#pragma unroll
    for (int nt = 0; nt < 8; ++nt) bb[0][nt] = wp[nt * 32 + lane];

    int rA = gr * CV_SS, rB = (gr + 8) * CV_SS;
    int rC = (gr + 16) * CV_SS, rD = (gr + 24) * CV_SS;

#pragma unroll
    for (int ks = 0; ks < 12; ++ks) {
        if (ks < 11) {
#pragma unroll
            for (int nt = 0; nt < 8; ++nt)
                bb[(ks + 1) & 1][nt] = wp[(ks + 1) * 256 + nt * 32 + lane];
        }
        int e0 = ks * 16 + tg * 2;
        int e1 = e0 + 1, e2 = e0 + 8, e3 = e0 + 9;
        int i0 = (e0 * 2731) >> 13, p0 = i0 * 10 + (e0 - i0 * 3) + wl;
        int i1 = (e1 * 2731) >> 13, p1 = i1 * 10 + (e1 - i1 * 3) + wl;
        int i2 = (e2 * 2731) >> 13, p2 = i2 * 10 + (e2 - i2 * 3) + wl;
        int i3 = (e3 * 2731) >> 13, p3 = i3 * 10 + (e3 - i3 * 3) + wl;

        uint32_t A0[4], A1[4];
        A0[0] = pack_h2(xs[rA + p0], xs[rA + p1]);
        A0[1] = pack_h2(xs[rB + p0], xs[rB + p1]);
        A0[2] = pack_h2(xs[rA + p2], xs[rA + p3]);
        A0[3] = pack_h2(xs[rB + p2], xs[rB + p3]);
        A1[0] = pack_h2(xs[rC + p0], xs[rC + p1]);
        A1[1] = pack_h2(xs[rD + p0], xs[rD + p1]);
        A1[2] = pack_h2(xs[rC + p2], xs[rC + p3]);
        A1[3] = pack_h2(xs[rD + p2], xs[rD + p3]);

        uint2* cur = bb[ks & 1];
#pragma unroll
        for (int nt = 0; nt < 8; ++nt) {
            asm volatile(
                "mma.sync.aligned.m16n8k16.row.col.f32.f16.f16.f32 "
                "{%0,%1,%2,%3}, {%4,%5,%6,%7}, {%8,%9}, {%0,%1,%2,%3};"
                : "+f"(acc[0][nt][0]), "+f"(acc[0][nt][1]),
                  "+f"(acc[0][nt][2]), "+f"(acc[0][nt][3])
                : "r"(A0[0]), "r"(A0[1]), "r"(A0[2]), "r"(A0[3]),
                  "r"(cur[nt].x), "r"(cur[nt].y));
            asm volatile(
                "mma.sync.aligned.m16n8k16.row.col.f32.f16.f16.f32 "
                "{%0,%1,%2,%3}, {%4,%5,%6,%7}, {%8,%9}, {%0,%1,%2,%3};"
                : "+f"(acc[1][nt][0]), "+f"(acc[1][nt][1]),
                  "+f"(acc[1][nt][2]), "+f"(acc[1][nt][3])
                : "r"(A1[0]), "r"(A1[1]), "r"(A1[2]), "r"(A1[3]),
                  "r"(cur[nt].x), "r"(cur[nt].y));
        }
    }
    __syncthreads();   // all warps done with xs — safe to overwrite with out-stage

    // stage: os[s][wl][o], stride CV_OSS per s (reuses xs region; sb beyond it)
    float* os = cs;
#pragma unroll
    for (int mt = 0; mt < 2; ++mt) {
        int sA = gr + mt * 16;
#pragma unroll
        for (int nt = 0; nt < 8; ++nt) {
            int o = nt * 8 + tg * 2;
            float2 bv = *reinterpret_cast<const float2*>(&sb[wl * 64 + o]);
            float2 v0, v1;
            v0.x = acc[mt][nt][0] + bv.x; v0.y = acc[mt][nt][1] + bv.y;
            v1.x = acc[mt][nt][2] + bv.x; v1.y = acc[mt][nt][3] + bv.y;
            *reinterpret_cast<float2*>(&os[sA * CV_OSS + wl * 64 + o]) = v0;
            *reinterpret_cast<float2*>(&os[(sA + 8) * CV_OSS + wl * 64 + o]) = v1;
        }
    }
    __syncthreads();

    // coalesced global writes: per (s,o) one row of 8 consecutive l's
    for (int p = tid; p < S2_ * CO_; p += 256) {
        int s = p >> 6, o = p & 63;
        const float* orow = os + s * CV_OSS + o;
        float4 v0, v1;
        v0.x = orow[0];   v0.y = orow[64];  v0.z = orow[128]; v0.w = orow[192];
        v1.x = orow[256]; v1.y = orow[320]; v1.z = orow[384]; v1.w = orow[448];
        float* dst = out + (((size_t)s * B_ + b) * CO_ + o) * L_ + l0;
        *reinterpret_cast<float4*>(dst) = v0;
        *reinterpret_cast<float4*>(dst + 4) = v1;
    }
}

// =================================================================
// launch
// =================================================================
extern "C" void kernel_launch(void* const* d_in, const int* in_sizes, int n_in,
                              void* d_out, int out_size)
{
    const float* x   = (const float*)d_in[0];
    const float* z   = (const float*)d_in[1];
    const float* W1  = (const float*)d_in[2];
    const float* b1  = (const float*)d_in[3];
    const float* g1  = (const float*)d_in[4];
    const float* be1 = (const float*)d_in[5];
    const float* W2  = (const float*)d_in[6];
    const float* b2  = (const float*)d_in[7];
    const float* Wb1 = (const float*)d_in[8];
    const float* bb1 = (const float*)d_in[9];
    const float* gb1 = (const float*)d_in[10];
    const float* beb1= (const float*)d_in[11];
    const float* Wb2 = (const float*)d_in[12];
    const float* bb2 = (const float*)d_in[13];
    float* out = (float*)d_out;

    cudaFuncSetAttribute(wgen_kernel, cudaFuncAttributeMaxDynamicSharedMemorySize, WG_SMEM_BYTES);
    cudaFuncSetAttribute(conv_kernel, cudaFuncAttributeMaxDynamicSharedMemorySize, CV_SMEM_BYTES);

    hyper_kernel<<<BL_, 128>>>(z, W1, b1, g1, be1, Wb1, bb1, gb1, beb1, Wb2, bb2);
    permute_kernel<<<(NW_ * H_ + 255) / 256, 256>>>(W2, b2);
    wgen_kernel<<<dim3(NW_ / 128, BL_ / 128), 256, WG_SMEM_BYTES>>>();
    conv_kernel<<<dim3(L_ / 8, B_), 256, CV_SMEM_BYTES>>>(x, out);
}